// round 1
// baseline (speedup 1.0000x reference)
#include <cuda_runtime.h>
#include <cstdint>
#include <cstddef>

// Problem dims
#define Bn 4096
#define Dn 256
#define Hn 2048
#define On 256

static constexpr size_t BH      = (size_t)Bn * Hn;          // 8,388,608
static constexpr size_t SE2_OFF = (size_t)8 * Bn * On;      // task_out elems = 8,388,608
static constexpr size_t SE3_OFF = SE2_OFF + (size_t)4 * BH; // + 33,554,432

// Scratch: per-task hidden activations (te), 8 * 4096 * 2048 fp32 = 256 MB (.bss, no alloc)
__device__ float g_te[(size_t)8 * Bn * Hn];
// Gates for all 18 experts: [18, B]
__device__ float g_gate[18 * Bn];

// Routing: which expert contributions feed each task output
__constant__ int c_cnt[8]    = {1, 3, 2, 2, 4, 2, 2, 2};
__constant__ int c_lst[8][4] = {
    {0, 0, 0, 0},
    {1, 8, 9, 0},
    {2, 10, 0, 0},
    {3, 11, 0, 0},
    {4, 12, 13, 14},
    {5, 15, 0, 0},
    {6, 16, 0, 0},
    {7, 17, 0, 0}
};

struct P {
    const float* x[8];
    const float* W_task; const float* b_task; const float* Wg_task; const float* bg_task;
    const float* Wo_task; const float* bo_task;
    const float* W_b2;  const float* b_b2;  const float* Wg_b2;  const float* bg_b2;
    const float* Wo_b2; const float* bo_b2;
    const float* W_b3;  const float* b_b3;  const float* Wg_b3;  const float* bg_b3;
    const float* Wo_b3; const float* bo_b3;
    float* out;
};

// ============================================================================
// Kernel 1: hidden = relu(X_e @ W_e + b_e) for 18 experts.
//   e 0..7  : task experts, K=256, A = x[e],             dst = g_te[e]
//   e 8..11 : b2 experts,   K=512, A = [x2 | x3],        dst = out + SE2
//   e 12..17: b3 experts,   K=768, A = [x5 | x6 | x7],   dst = out + SE3
// Tile 128x128x8, 256 threads, 8x8 microtile.
// ============================================================================
__global__ __launch_bounds__(256) void k_hidden(P p) {
    const int e = blockIdx.z;
    const float* xp0; const float* xp1 = nullptr; const float* xp2 = nullptr;
    int K; const float* W; const float* bias; float* dst;
    if (e < 8) {
        K = 256; xp0 = p.x[e];
        W = p.W_task + (size_t)e * Dn * Hn;
        bias = p.b_task + e * Hn;
        dst = g_te + (size_t)e * BH;
    } else if (e < 12) {
        const int q = e - 8;
        K = 512; xp0 = p.x[2]; xp1 = p.x[3];
        W = p.W_b2 + (size_t)q * 512 * Hn;
        bias = p.b_b2 + q * Hn;
        dst = p.out + SE2_OFF + (size_t)q * BH;
    } else {
        const int q = e - 12;
        K = 768; xp0 = p.x[5]; xp1 = p.x[6]; xp2 = p.x[7];
        W = p.W_b3 + (size_t)q * 768 * Hn;
        bias = p.b_b3 + q * Hn;
        dst = p.out + SE3_OFF + (size_t)q * BH;
    }

    __shared__ float As[8][128];
    __shared__ float Bs[8][128];

    const int tid = threadIdx.x;
    const int tx = tid & 15, ty = tid >> 4;
    const int row0 = blockIdx.y * 128, col0 = blockIdx.x * 128;
    const int a_row = tid >> 1, a_k4 = (tid & 1) * 4;
    const int b_k = tid >> 5,  b_n  = (tid & 31) * 4;

    float acc[8][8];
#pragma unroll
    for (int i = 0; i < 8; i++)
#pragma unroll
        for (int j = 0; j < 8; j++) acc[i][j] = 0.f;

    for (int k0 = 0; k0 < K; k0 += 8) {
        const int gk = k0 + a_k4;
        const int part = gk >> 8;
        const float* xa = (part == 0) ? xp0 : ((part == 1) ? xp1 : xp2);
        const float4 av = *(const float4*)(xa + (size_t)(row0 + a_row) * Dn + (gk & 255));
        As[a_k4 + 0][a_row] = av.x;
        As[a_k4 + 1][a_row] = av.y;
        As[a_k4 + 2][a_row] = av.z;
        As[a_k4 + 3][a_row] = av.w;
        const float4 bv = *(const float4*)(W + (size_t)(k0 + b_k) * Hn + col0 + b_n);
        *(float4*)(&Bs[b_k][b_n]) = bv;
        __syncthreads();
#pragma unroll
        for (int kk = 0; kk < 8; kk++) {
            float a[8], b[8];
            *(float4*)(a)     = *(const float4*)(&As[kk][ty * 4]);
            *(float4*)(a + 4) = *(const float4*)(&As[kk][ty * 4 + 64]);
            *(float4*)(b)     = *(const float4*)(&Bs[kk][tx * 4]);
            *(float4*)(b + 4) = *(const float4*)(&Bs[kk][tx * 4 + 64]);
#pragma unroll
            for (int i = 0; i < 8; i++)
#pragma unroll
                for (int j = 0; j < 8; j++)
                    acc[i][j] = fmaf(a[i], b[j], acc[i][j]);
        }
        __syncthreads();
    }

    // Epilogue: bias + relu, store
#pragma unroll
    for (int i = 0; i < 8; i++) {
        const int r = row0 + ((i < 4) ? (ty * 4 + i) : (64 + ty * 4 + (i - 4)));
#pragma unroll
        for (int jh = 0; jh < 2; jh++) {
            const int c = col0 + tx * 4 + jh * 64;
            float4 o;
            o.x = fmaxf(acc[i][jh * 4 + 0] + bias[c + 0], 0.f);
            o.y = fmaxf(acc[i][jh * 4 + 1] + bias[c + 1], 0.f);
            o.z = fmaxf(acc[i][jh * 4 + 2] + bias[c + 2], 0.f);
            o.w = fmaxf(acc[i][jh * 4 + 3] + bias[c + 3], 0.f);
            *(float4*)(&dst[(size_t)r * Hn + c]) = o;
        }
    }
}

// ============================================================================
// Kernel 2: gates.
//   e 0..7  : gt = sigmoid(x[e] . Wg_task[e] + bg)   (K=256, on the INPUT)
//   e 8..11 : g2 = sigmoid(se2 . Wg_b2 + bg)          (K=2048, on the hidden)
//   e 12..17: g3 = sigmoid(se3 . Wg_b3 + bg)
// One 128-thread block per (expert, row).
// ============================================================================
__global__ __launch_bounds__(128) void k_gate(P p) {
    const int e = blockIdx.y;
    const int row = blockIdx.x;
    const float* src; const float* wg; float bg; int K;
    if (e < 8) {
        src = p.x[e] + (size_t)row * Dn;
        wg = p.Wg_task + e * Dn; bg = p.bg_task[e]; K = Dn;
    } else if (e < 12) {
        const int q = e - 8;
        src = p.out + SE2_OFF + (size_t)q * BH + (size_t)row * Hn;
        wg = p.Wg_b2 + q * Hn; bg = p.bg_b2[q]; K = Hn;
    } else {
        const int q = e - 12;
        src = p.out + SE3_OFF + (size_t)q * BH + (size_t)row * Hn;
        wg = p.Wg_b3 + q * Hn; bg = p.bg_b3[q]; K = Hn;
    }
    float s = 0.f;
    for (int i = threadIdx.x; i < K; i += 128) s += src[i] * wg[i];
    __shared__ float red[128];
    red[threadIdx.x] = s;
    __syncthreads();
#pragma unroll
    for (int o = 64; o > 0; o >>= 1) {
        if (threadIdx.x < o) red[threadIdx.x] += red[threadIdx.x + o];
        __syncthreads();
    }
    if (threadIdx.x == 0)
        g_gate[e * Bn + row] = 1.f / (1.f + expf(-(red[0] + bg)));
}

// ============================================================================
// Kernel 3: task_out[t] = sum_{e in list(t)} (g_e (.) hid_e) @ Wo_e + bo_e
// Tile 128x128x8, accumulate all routed contributions in one CTA (no atomics).
// Gate applied as per-row scale on A while staging into smem.
// ============================================================================
__global__ __launch_bounds__(256) void k_out(P p) {
    const int t = blockIdx.z;
    const int row0 = blockIdx.y * 128, col0 = blockIdx.x * 128;

    __shared__ float As[8][128];
    __shared__ float Bs[8][128];
    __shared__ float gs[128];

    const int tid = threadIdx.x;
    const int tx = tid & 15, ty = tid >> 4;
    const int a_row = tid >> 1, a_k4 = (tid & 1) * 4;
    const int b_k = tid >> 5,  b_n  = (tid & 31) * 4;

    float acc[8][8];
#pragma unroll
    for (int i = 0; i < 8; i++)
#pragma unroll
        for (int j = 0; j < 8; j++) acc[i][j] = 0.f;

    const int nc = c_cnt[t];
    for (int ci = 0; ci < nc; ci++) {
        const int e = c_lst[t][ci];
        const float* hid; const float* Wo;
        if (e < 8) {
            hid = g_te + (size_t)e * BH;
            Wo = p.Wo_task + (size_t)e * Hn * On;
        } else if (e < 12) {
            hid = p.out + SE2_OFF + (size_t)(e - 8) * BH;
            Wo = p.Wo_b2 + (size_t)(e - 8) * Hn * On;
        } else {
            hid = p.out + SE3_OFF + (size_t)(e - 12) * BH;
            Wo = p.Wo_b3 + (size_t)(e - 12) * Hn * On;
        }
        if (tid < 128) gs[tid] = g_gate[e * Bn + row0 + tid];
        __syncthreads();

        for (int k0 = 0; k0 < Hn; k0 += 8) {
            const float g = gs[a_row];
            const float4 av = *(const float4*)(hid + (size_t)(row0 + a_row) * Hn + k0 + a_k4);
            As[a_k4 + 0][a_row] = av.x * g;
            As[a_k4 + 1][a_row] = av.y * g;
            As[a_k4 + 2][a_row] = av.z * g;
            As[a_k4 + 3][a_row] = av.w * g;
            const float4 bv = *(const float4*)(Wo + (size_t)(k0 + b_k) * On + col0 + b_n);
            *(float4*)(&Bs[b_k][b_n]) = bv;
            __syncthreads();
#pragma unroll
            for (int kk = 0; kk < 8; kk++) {
                float a[8], b[8];
                *(float4*)(a)     = *(const float4*)(&As[kk][ty * 4]);
                *(float4*)(a + 4) = *(const float4*)(&As[kk][ty * 4 + 64]);
                *(float4*)(b)     = *(const float4*)(&Bs[kk][tx * 4]);
                *(float4*)(b + 4) = *(const float4*)(&Bs[kk][tx * 4 + 64]);
#pragma unroll
                for (int i = 0; i < 8; i++)
#pragma unroll
                    for (int j = 0; j < 8; j++)
                        acc[i][j] = fmaf(a[i], b[j], acc[i][j]);
            }
            __syncthreads();
        }
    }

    // Epilogue: add summed biases of all contributions, write task_out
#pragma unroll
    for (int i = 0; i < 8; i++) {
        const int r = row0 + ((i < 4) ? (ty * 4 + i) : (64 + ty * 4 + (i - 4)));
#pragma unroll
        for (int jh = 0; jh < 2; jh++) {
            const int c = col0 + tx * 4 + jh * 64;
            float4 o;
            o.x = acc[i][jh * 4 + 0];
            o.y = acc[i][jh * 4 + 1];
            o.z = acc[i][jh * 4 + 2];
            o.w = acc[i][jh * 4 + 3];
            for (int ci = 0; ci < nc; ci++) {
                const int e = c_lst[t][ci];
                const float* bo = (e < 8) ? (p.bo_task + e * On)
                                 : (e < 12) ? (p.bo_b2 + (e - 8) * On)
                                            : (p.bo_b3 + (e - 12) * On);
                o.x += bo[c + 0]; o.y += bo[c + 1]; o.z += bo[c + 2]; o.w += bo[c + 3];
            }
            *(float4*)(&p.out[(size_t)t * Bn * On + (size_t)r * On + c]) = o;
        }
    }
}

// ============================================================================
extern "C" void kernel_launch(void* const* d_in, const int* in_sizes, int n_in,
                              void* d_out, int out_size) {
    P p;
    for (int i = 0; i < 8; i++) p.x[i] = (const float*)d_in[i];
    p.W_task  = (const float*)d_in[8];
    p.b_task  = (const float*)d_in[9];
    p.Wg_task = (const float*)d_in[10];
    p.bg_task = (const float*)d_in[11];
    p.Wo_task = (const float*)d_in[12];
    p.bo_task = (const float*)d_in[13];
    p.W_b2    = (const float*)d_in[14];
    p.b_b2    = (const float*)d_in[15];
    p.Wg_b2   = (const float*)d_in[16];
    p.bg_b2   = (const float*)d_in[17];
    p.Wo_b2   = (const float*)d_in[18];
    p.bo_b2   = (const float*)d_in[19];
    p.W_b3    = (const float*)d_in[20];
    p.b_b3    = (const float*)d_in[21];
    p.Wg_b3   = (const float*)d_in[22];
    p.bg_b3   = (const float*)d_in[23];
    p.Wo_b3   = (const float*)d_in[24];
    p.bo_b3   = (const float*)d_in[25];
    p.out = (float*)d_out;

    dim3 g1(Hn / 128, Bn / 128, 18);   // 16 x 32 x 18 = 9216 CTAs
    k_hidden<<<g1, 256>>>(p);

    dim3 g2(Bn, 18);                   // 73728 small blocks
    k_gate<<<g2, 128>>>(p);

    dim3 g3(On / 128, Bn / 128, 8);    // 2 x 32 x 8 = 512 CTAs
    k_out<<<g3, 256>>>(p);
}